// round 6
// baseline (speedup 1.0000x reference)
#include <cuda_runtime.h>
#include <cuda_fp16.h>
#include <math.h>

#define N_IMG 128
#define N_ANG 285
#define N_DET 183
#define N_T   384

#define PITCHE 133          // smem row pitch in 8-byte entries
#define PROWS  131
#define SMEM_E     (PROWS * PITCHE)
#define SMEM_BYTES (SMEM_E * 8)

#define THREADS 768         // 4 k-segments x 192 threads
#define SEGLEN  96

__global__ __launch_bounds__(THREADS)
void radon_fwd_kernel(const float* __restrict__ x, float* __restrict__ out) {
    extern __shared__ uint2 simg[];     // entry = {half2 AB, half2 CD} : 4 batches
    __shared__ float4 part[THREADS];
    __shared__ double geo[6];
    __shared__ float  stf[2];

    const int tid = threadIdx.x;
    const int ang = blockIdx.x;
    const int bq  = blockIdx.y;         // batch quad (0..1)

    const double RHO = 20.0 * sqrt(2.0);
    const double DX  = 0.3125;
    const double DT  = 2.0 * RHO / (double)N_T;
    const float  SCALE = (float)(DT / 12.0);

    if (tid == 0) {
        double a = ((double)ang + 0.5) * M_PI / (double)N_ANG;
        double dsin = sin(a), dcos = cos(a);
        double tb = -RHO + 0.5 * DT;
        double st0 = DT * dcos / DX;
        double st1 = DT * dsin / DX;
        geo[0] = -dsin / DX;
        geo[1] = (tb * dcos + 20.0) / DX + 0.5;
        geo[2] =  dcos / DX;
        geo[3] = (tb * dsin + 20.0) / DX + 0.5;
        geo[4] = (fabs(st0) < 1e-9) ? 0.0 : 1.0 / st0;
        geo[5] = (fabs(st1) < 1e-9) ? 0.0 : 1.0 / st1;
        stf[0] = (float)st0;
        stf[1] = (float)st1;
    }

    // Interior fill: 4 images interleaved as {AB, CD} half2 pairs
    {
        const float4* iA4 = (const float4*)(x + (size_t)(4 * bq + 0) * N_IMG * N_IMG);
        const float4* iB4 = (const float4*)(x + (size_t)(4 * bq + 1) * N_IMG * N_IMG);
        const float4* iC4 = (const float4*)(x + (size_t)(4 * bq + 2) * N_IMG * N_IMG);
        const float4* iD4 = (const float4*)(x + (size_t)(4 * bq + 3) * N_IMG * N_IMG);
        for (int q = tid; q < N_IMG * N_IMG / 4; q += THREADS) {
            float4 a4 = iA4[q];
            float4 b4 = iB4[q];
            float4 c4 = iC4[q];
            float4 d4 = iD4[q];
            int r = q >> 5;
            int c = (q & 31) << 2;
            uint2* dst = &simg[(r + 1) * PITCHE + (c + 1)];
            uint2 e;
            __half2 h;
            h = __floats2half2_rn(a4.x, b4.x); e.x = *(unsigned*)&h;
            h = __floats2half2_rn(c4.x, d4.x); e.y = *(unsigned*)&h; dst[0] = e;
            h = __floats2half2_rn(a4.y, b4.y); e.x = *(unsigned*)&h;
            h = __floats2half2_rn(c4.y, d4.y); e.y = *(unsigned*)&h; dst[1] = e;
            h = __floats2half2_rn(a4.z, b4.z); e.x = *(unsigned*)&h;
            h = __floats2half2_rn(c4.z, d4.z); e.y = *(unsigned*)&h; dst[2] = e;
            h = __floats2half2_rn(a4.w, b4.w); e.x = *(unsigned*)&h;
            h = __floats2half2_rn(c4.w, d4.w); e.y = *(unsigned*)&h; dst[3] = e;
        }
    }
    // Zero only the readable border ring
    {
        const uint2 z = make_uint2(0u, 0u);
        for (int c = tid; c < 130; c += THREADS) {
            simg[c] = z;
            simg[129 * PITCHE + c] = z;
        }
        for (int r = 1 + tid; r <= 128; r += THREADS) {
            simg[r * PITCHE] = z;
            simg[r * PITCHE + 129] = z;
        }
    }
    __syncthreads();

    const int det = tid % 192;
    const int seg = tid / 192;          // 0..3

    float accA = 0.0f, accB = 0.0f, accC = 0.0f, accD = 0.0f;

    if (det < N_DET) {
        double s = -RHO + ((double)det + 0.5) * (2.0 * RHO / (double)N_DET);
        double b0d = fma(s, geo[0], geo[1]);
        double b1d = fma(s, geo[2], geo[3]);

        const double EPS = 2e-4;
        int klo = seg * SEGLEN;
        int khi = klo + SEGLEN;
        {
            double bases[2] = {b0d, b1d};
            #pragma unroll
            for (int ax = 0; ax < 2; ++ax) {
                double bs = bases[ax], is = geo[4 + ax];
                if (is == 0.0) {
                    if (bs < EPS || bs > 129.0 - EPS) klo = khi;
                } else {
                    double t0 = (EPS - bs) * is;
                    double t1 = ((129.0 - EPS) - bs) * is;
                    double lo = fmin(t0, t1), hi = fmax(t0, t1);
                    int kl = (int)ceil(lo);
                    int kh = (int)floor(hi) + 1;
                    if (kl > klo) klo = kl;
                    if (kh < khi) khi = kh;
                }
            }
        }
        if (khi < klo) khi = klo;

        const float b0 = (float)b0d, s0 = stf[0];
        const float b1 = (float)b1d, s1 = stf[1];
        const float b0p = b0 + s0;
        const float b1p = b1 + s1;

        int n = khi - klo;
        float kf = (float)klo;

        #define SAMPLE(F0, F1, RAB, RCD)                                       \
        {                                                                      \
            float fl0 = floorf(F0);                                            \
            float fl1 = floorf(F1);                                            \
            float fa  = (F0) - fl0;                                            \
            float fb  = (F1) - fl1;                                            \
            int boff = (int)fmaf(fl0, (float)(PITCHE * 8), fl1 * 8.0f);        \
            const uint2* p = (const uint2*)((const char*)simg + boff);         \
            uint2 w00 = p[0];                                                  \
            uint2 w01 = p[1];                                                  \
            uint2 w10 = p[PITCHE];                                             \
            uint2 w11 = p[PITCHE + 1];                                         \
            __half2 b2 = __float2half2_rn(fb);                                 \
            __half2 a2 = __float2half2_rn(fa);                                 \
            __half2 u00 = *(__half2*)&w00.x, q00 = *(__half2*)&w00.y;          \
            __half2 u01 = *(__half2*)&w01.x, q01 = *(__half2*)&w01.y;          \
            __half2 u10 = *(__half2*)&w10.x, q10 = *(__half2*)&w10.y;          \
            __half2 u11 = *(__half2*)&w11.x, q11 = *(__half2*)&w11.y;          \
            __half2 t0 = __hfma2(b2, __hsub2(u01, u00), u00);                  \
            __half2 t1 = __hfma2(b2, __hsub2(u11, u10), u10);                  \
            RAB = __hfma2(a2, __hsub2(t1, t0), t0);                            \
            __half2 t2 = __hfma2(b2, __hsub2(q01, q00), q00);                  \
            __half2 t3 = __hfma2(b2, __hsub2(q11, q10), q10);                  \
            RCD = __hfma2(a2, __hsub2(t3, t2), t2);                            \
        }

        int npair = n >> 1;
        #pragma unroll 2
        for (int it = 0; it < npair; ++it, kf += 2.0f) {
            float f0a = fmaf(kf, s0, b0);
            float f1a = fmaf(kf, s1, b1);
            float f0b = fmaf(kf, s0, b0p);
            float f1b = fmaf(kf, s1, b1p);
            __half2 rab0, rcd0, rab1, rcd1;
            SAMPLE(f0a, f1a, rab0, rcd0)
            SAMPLE(f0b, f1b, rab1, rcd1)
            __half2 rab = __hadd2(rab0, rab1);
            __half2 rcd = __hadd2(rcd0, rcd1);
            float2 fab = __half22float2(rab);
            float2 fcd = __half22float2(rcd);
            accA += fab.x; accB += fab.y;
            accC += fcd.x; accD += fcd.y;
        }
        if (n & 1) {
            float f0a = fmaf(kf, s0, b0);
            float f1a = fmaf(kf, s1, b1);
            __half2 rab, rcd;
            SAMPLE(f0a, f1a, rab, rcd)
            float2 fab = __half22float2(rab);
            float2 fcd = __half22float2(rcd);
            accA += fab.x; accB += fab.y;
            accC += fcd.x; accD += fcd.y;
        }
        #undef SAMPLE
    }

    part[tid] = make_float4(accA, accB, accC, accD);
    __syncthreads();

    if (tid < N_DET) {
        float4 p0 = part[tid];
        float4 p1 = part[tid + 192];
        float4 p2 = part[tid + 384];
        float4 p3 = part[tid + 576];
        float rA = (p0.x + p1.x + p2.x + p3.x) * SCALE;
        float rB = (p0.y + p1.y + p2.y + p3.y) * SCALE;
        float rC = (p0.z + p1.z + p2.z + p3.z) * SCALE;
        float rD = (p0.w + p1.w + p2.w + p3.w) * SCALE;
        size_t o = ((size_t)(4 * bq) * N_ANG + ang) * N_DET + tid;
        size_t stride = (size_t)N_ANG * N_DET;
        out[o] = rA;
        out[o + stride] = rB;
        out[o + 2 * stride] = rC;
        out[o + 3 * stride] = rD;
    }
}

extern "C" void kernel_launch(void* const* d_in, const int* in_sizes, int n_in,
                              void* d_out, int out_size) {
    const float* x = (const float*)d_in[0];
    float* out = (float*)d_out;
    cudaFuncSetAttribute(radon_fwd_kernel,
                         cudaFuncAttributeMaxDynamicSharedMemorySize, SMEM_BYTES);
    dim3 grid(N_ANG, 2);
    radon_fwd_kernel<<<grid, THREADS, SMEM_BYTES>>>(x, out);
}

// round 7
// speedup vs baseline: 1.2149x; 1.2149x over previous
#include <cuda_runtime.h>
#include <cuda_fp16.h>
#include <math.h>

#define N_IMG 128
#define N_ANG 285
#define N_DET 183
#define N_T   384

#define PITCH2 133
#define PROWS  131
#define SMEM_H2    (PROWS * PITCH2)
#define SMEM_BYTES (SMEM_H2 * 4)

#define THREADS 384         // 2 k-segments x 192 threads

__global__ __launch_bounds__(THREADS)
void radon_fwd_kernel(const float* __restrict__ x, float* __restrict__ out) {
    extern __shared__ __half2 simg[];
    __shared__ float2 part[THREADS];
    __shared__ double geo[6];
    __shared__ float  stf[2];

    const int tid = threadIdx.x;
    const int ang = blockIdx.x;
    const int bp  = blockIdx.y;

    const double RHO = 20.0 * sqrt(2.0);
    const double DX  = 0.3125;
    const double DT  = 2.0 * RHO / (double)N_T;
    const float  SCALE = (float)(DT / 12.0);

    if (tid == 0) {
        double a = ((double)ang + 0.5) * M_PI / (double)N_ANG;
        double dsin = sin(a), dcos = cos(a);
        double tb = -RHO + 0.5 * DT;
        double st0 = DT * dcos / DX;
        double st1 = DT * dsin / DX;
        geo[0] = -dsin / DX;
        geo[1] = (tb * dcos + 20.0) / DX + 0.5;
        geo[2] =  dcos / DX;
        geo[3] = (tb * dsin + 20.0) / DX + 0.5;
        geo[4] = (fabs(st0) < 1e-9) ? 0.0 : 1.0 / st0;
        geo[5] = (fabs(st1) < 1e-9) ? 0.0 : 1.0 / st1;
        stf[0] = (float)st0;
        stf[1] = (float)st1;
    }

    // Interior fill, vectorized
    const float4* iA4 = (const float4*)(x + (size_t)(2 * bp) * N_IMG * N_IMG);
    const float4* iB4 = (const float4*)(x + (size_t)(2 * bp + 1) * N_IMG * N_IMG);
    for (int q = tid; q < N_IMG * N_IMG / 4; q += THREADS) {
        float4 a4 = iA4[q];
        float4 b4 = iB4[q];
        int r = q >> 5;
        int c = (q & 31) << 2;
        __half2* dst = &simg[(r + 1) * PITCH2 + (c + 1)];
        dst[0] = __floats2half2_rn(a4.x, b4.x);
        dst[1] = __floats2half2_rn(a4.y, b4.y);
        dst[2] = __floats2half2_rn(a4.z, b4.z);
        dst[3] = __floats2half2_rn(a4.w, b4.w);
    }
    // Zero only the readable border ring
    {
        const __half2 z = __floats2half2_rn(0.0f, 0.0f);
        for (int c = tid; c < 130; c += THREADS) {
            simg[c] = z;
            simg[129 * PITCH2 + c] = z;
        }
        for (int r = 1 + tid; r <= 128; r += THREADS) {
            simg[r * PITCH2] = z;
            simg[r * PITCH2 + 129] = z;
        }
    }
    __syncthreads();

    const int det = tid % 192;
    const int seg = tid / 192;

    float accA0 = 0.0f, accB0 = 0.0f;
    float accA1 = 0.0f, accB1 = 0.0f;

    if (det < N_DET) {
        double s = -RHO + ((double)det + 0.5) * (2.0 * RHO / (double)N_DET);
        double b0d = fma(s, geo[0], geo[1]);
        double b1d = fma(s, geo[2], geo[3]);

        const double EPS = 2e-4;
        int klo = seg * 192;
        int khi = klo + 192;
        {
            double bases[2] = {b0d, b1d};
            #pragma unroll
            for (int ax = 0; ax < 2; ++ax) {
                double bs = bases[ax], is = geo[4 + ax];
                if (is == 0.0) {
                    if (bs < EPS || bs > 129.0 - EPS) klo = khi;
                } else {
                    double t0 = (EPS - bs) * is;
                    double t1 = ((129.0 - EPS) - bs) * is;
                    double lo = fmin(t0, t1), hi = fmax(t0, t1);
                    int kl = (int)ceil(lo);
                    int kh = (int)floor(hi) + 1;
                    if (kl > klo) klo = kl;
                    if (kh < khi) khi = kh;
                }
            }
        }
        if (khi < klo) khi = klo;

        const float b0 = (float)b0d, s0 = stf[0];
        const float b1 = (float)b1d, s1 = stf[1];
        const float b0p = b0 + s0;
        const float b1p = b1 + s1;

        int n = khi - klo;
        float kf = (float)klo;

        #define SAMPLE(F0, F1, OUT2)                                           \
        {                                                                      \
            float fl0 = floorf(F0);                                            \
            float fl1 = floorf(F1);                                            \
            float fa  = (F0) - fl0;                                            \
            float fb  = (F1) - fl1;                                            \
            int boff = (int)fmaf(fl0, (float)(PITCH2 * 4), fl1 * 4.0f);        \
            const __half2* p = (const __half2*)((const char*)simg + boff);     \
            __half2 v00 = p[0];                                                \
            __half2 v01 = p[1];                                                \
            __half2 v10 = p[PITCH2];                                           \
            __half2 v11 = p[PITCH2 + 1];                                       \
            __half2 b2 = __float2half2_rn(fb);                                 \
            __half2 a2 = __float2half2_rn(fa);                                 \
            __half2 top = __hfma2(b2, __hsub2(v01, v00), v00);                 \
            __half2 bot = __hfma2(b2, __hsub2(v11, v10), v10);                 \
            OUT2 = __hfma2(a2, __hsub2(bot, top), top);                        \
        }

        int npair = n >> 1;
        #pragma unroll 4
        for (int it = 0; it < npair; ++it, kf += 2.0f) {
            float f0a = fmaf(kf, s0, b0);
            float f1a = fmaf(kf, s1, b1);
            float f0b = fmaf(kf, s0, b0p);
            float f1b = fmaf(kf, s1, b1p);
            __half2 ra, rb;
            SAMPLE(f0a, f1a, ra)
            SAMPLE(f0b, f1b, rb)
            __half2 rs = __hadd2(ra, rb);
            float2 rf = __half22float2(rs);
            if (it & 1) { accA1 += rf.x; accB1 += rf.y; }
            else        { accA0 += rf.x; accB0 += rf.y; }
        }
        if (n & 1) {
            float f0a = fmaf(kf, s0, b0);
            float f1a = fmaf(kf, s1, b1);
            __half2 ra;
            SAMPLE(f0a, f1a, ra)
            float2 rf = __half22float2(ra);
            accA0 += rf.x;
            accB0 += rf.y;
        }
        #undef SAMPLE
    }

    part[tid] = make_float2(accA0 + accA1, accB0 + accB1);
    __syncthreads();

    if (tid < N_DET) {
        float2 p0 = part[tid];
        float2 p1 = part[tid + 192];
        float rA = (p0.x + p1.x) * SCALE;
        float rB = (p0.y + p1.y) * SCALE;
        size_t baseA = ((size_t)(2 * bp)     * N_ANG + ang) * N_DET + tid;
        size_t baseB = ((size_t)(2 * bp + 1) * N_ANG + ang) * N_DET + tid;
        out[baseA] = rA;
        out[baseB] = rB;
    }
}

extern "C" void kernel_launch(void* const* d_in, const int* in_sizes, int n_in,
                              void* d_out, int out_size) {
    const float* x = (const float*)d_in[0];
    float* out = (float*)d_out;
    cudaFuncSetAttribute(radon_fwd_kernel,
                         cudaFuncAttributeMaxDynamicSharedMemorySize, SMEM_BYTES);
    dim3 grid(N_ANG, 4);
    radon_fwd_kernel<<<grid, THREADS, SMEM_BYTES>>>(x, out);
}